// round 7
// baseline (speedup 1.0000x reference)
#include <cuda_runtime.h>
#include <cuda_bf16.h>

// DynamicMaskHead fused kernel (R7 = R6 with transpose-fill range fix):
//   k-outer MLP loops with weights transposed to [k][c] in smem -> weight
//   loads become LDS.128 (2 per k-step feeding 32 independent FFMAs),
//   removing the scalar-LDS scoreboard stalls that pinned issue% at ~25%.
//   R6 bug: w2/wf transpose used tid range [96,160) but block has 128
//   threads -> upper half of those matrices was uninitialized.
//
// Shapes (fixed): feats [2,8,100,152] f32, params [128,419] f32,
//                 out = 3 x [128,1,200,304] f32 concatenated (b,e,f).

#define Hh   100
#define Wd   152
#define HWd  15200
#define OH   200
#define OW   304
#define OT   24      // output rows per block tile (9 tiles)
#define LR   14      // max logits rows per tile (12 + 2 halo)
#define NPAR 419
#define NT   128     // threads per block

// load 8 consecutive floats from 16B-aligned smem as 2x LDS.128
__device__ __forceinline__ void lds8(const float* __restrict__ base, float w[8]) {
    const float4 a = *(const float4*)base;
    const float4 b = *(const float4*)(base + 4);
    w[0] = a.x; w[1] = a.y; w[2] = a.z; w[3] = a.w;
    w[4] = b.x; w[5] = b.y; w[6] = b.z; w[7] = b.w;
}

__global__ void __launch_bounds__(NT, 4)
dmh_kernel(const float* __restrict__ feats_b,
           const float* __restrict__ feats_e,
           const float* __restrict__ params,
           const float* __restrict__ locs,
           const float* __restrict__ soi_arr,
           const int*   __restrict__ im_inds,
           const int*   __restrict__ fpn,
           const int*   __restrict__ stride_ptr,
           float*       __restrict__ out,
           int n_inst)
{
    const int tid  = threadIdx.x;
    const int tile = blockIdx.x;
    const int inst = blockIdx.y;
    const int i0   = tile * OT;

    __shared__ __align__(16) float sp[NPAR];
    __shared__ __align__(16) float sl[3][LR][Wd];
    __shared__ float sxs[32][NT];           // per-thread scratch: x2b[8ch][4pos]
    // transposed weights [k][c] (16B aligned) + aligned bias copies
    __shared__ __align__(16) float w1bT[80], w1eT[80];
    __shared__ __align__(16) float w2bT[64], w2eT[64], wf1T[64];
    __shared__ __align__(16) float w3bA[8], w3eA[8], b1bA[8], b1eA[8];
    __shared__ __align__(16) float b2bA[8], b2eA[8], wf2A[8], bf1A[8];

    const float* prow = params + inst * NPAR;
    for (int t = tid; t < NPAR; t += NT) sp[t] = prow[t];
    __syncthreads();

    // transpose weights to [k][c]; copy misaligned biases into aligned arrays
    if (tid < 80) {                               // 80 threads: w1 (10x8)
        const int k = tid >> 3, c = tid & 7;
        w1bT[tid] = sp[c * 10 + k];
        w1eT[tid] = sp[169 + c * 10 + k];
    }
    if (tid >= 64) {                              // 64 threads: w2/wf (8x8)
        const int t = tid - 64;
        const int k = t >> 3, c = t & 7;
        w2bT[t] = sp[80 + c * 8 + k];
        w2eT[t] = sp[249 + c * 8 + k];
        wf1T[t] = sp[338 + c * 8 + k];
    }
    if (tid < 8) {                                // 8 threads: bias/out-weight
        w3bA[tid] = sp[144 + tid];  w3eA[tid] = sp[313 + tid];
        b1bA[tid] = sp[152 + tid];  b1eA[tid] = sp[321 + tid];
        b2bA[tid] = sp[160 + tid];  b2eA[tid] = sp[329 + tid];
        wf2A[tid] = sp[402 + tid];  bf1A[tid] = sp[410 + tid];
    }

    const int   stride  = stride_ptr ? *stride_ptr : 8;
    const float fstride = (float)stride;
    const float halfs   = (float)(stride >> 1);

    const float ix  = locs[inst * 2 + 0];
    const float iy  = locs[inst * 2 + 1];
    const float inv = 1.0f / soi_arr[fpn[inst]];
    const int   im  = im_inds[inst];

    const int ybase = (i0 > 0) ? ((i0 - 1) >> 1) : 0;
    const int yend  = min(Hh - 1, ((i0 + OT - 2) >> 1) + 1);
    const int nrows = yend - ybase + 1;

    __syncthreads();

    const float b3b = sp[168], b3e = sp[337], bf2 = sp[418];

    const float* fbB = feats_b + (long long)im * 8 * HWd;
    const float* fbE = feats_e + (long long)im * 8 * HWd;

    // ---------------- Phase B: logits strip into smem ----------------
    const int ngroups = nrows * (Wd / 4);      // 38 col-groups per row
    for (int g = tid; g < ngroups; g += NT) {
        const int srow = g / 38;
        const int c0   = (g - srow * 38) * 4;
        const int y    = ybase + srow;

        const float rely = (iy - ((float)y * fstride + halfs)) * inv;
        float relx[4];
#pragma unroll
        for (int p = 0; p < 4; p++)
            relx[p] = (ix - ((float)(c0 + p) * fstride + halfs)) * inv;

        const int base = y * Wd + c0;
        float w[8];

        // ================= PASS 1: body head =================
        {
            float4 f[8];
#pragma unroll
            for (int k = 0; k < 8; k++)
                f[k] = *(const float4*)(fbB + k * HWd + base);

            // layer1: acc[c][p], k-outer
            float acc[8][4];
            lds8(b1bA, w);
#pragma unroll
            for (int c = 0; c < 8; c++)
#pragma unroll
                for (int p = 0; p < 4; p++) acc[c][p] = w[c];
            lds8(w1bT, w);                          // k=0: relx
#pragma unroll
            for (int c = 0; c < 8; c++)
#pragma unroll
                for (int p = 0; p < 4; p++) acc[c][p] = fmaf(w[c], relx[p], acc[c][p]);
            lds8(w1bT + 8, w);                      // k=1: rely
#pragma unroll
            for (int c = 0; c < 8; c++)
#pragma unroll
                for (int p = 0; p < 4; p++) acc[c][p] = fmaf(w[c], rely, acc[c][p]);
#pragma unroll
            for (int k = 0; k < 8; k++) {
                lds8(w1bT + 16 + k * 8, w);
                const float v0 = f[k].x, v1 = f[k].y, v2 = f[k].z, v3 = f[k].w;
#pragma unroll
                for (int c = 0; c < 8; c++) {
                    acc[c][0] = fmaf(w[c], v0, acc[c][0]);
                    acc[c][1] = fmaf(w[c], v1, acc[c][1]);
                    acc[c][2] = fmaf(w[c], v2, acc[c][2]);
                    acc[c][3] = fmaf(w[c], v3, acc[c][3]);
                }
            }
            // relu in place -> x1
#pragma unroll
            for (int c = 0; c < 8; c++)
#pragma unroll
                for (int p = 0; p < 4; p++) acc[c][p] = fmaxf(acc[c][p], 0.0f);

            // layer2
            float a2[8][4];
            lds8(b2bA, w);
#pragma unroll
            for (int c = 0; c < 8; c++)
#pragma unroll
                for (int p = 0; p < 4; p++) a2[c][p] = w[c];
#pragma unroll
            for (int k = 0; k < 8; k++) {
                lds8(w2bT + k * 8, w);
#pragma unroll
                for (int c = 0; c < 8; c++)
#pragma unroll
                    for (int p = 0; p < 4; p++)
                        a2[c][p] = fmaf(w[c], acc[k][p], a2[c][p]);
            }
            // layer3 + stage x2b
            lds8(w3bA, w);
            float lb[4] = {b3b, b3b, b3b, b3b};
#pragma unroll
            for (int c = 0; c < 8; c++)
#pragma unroll
                for (int p = 0; p < 4; p++) {
                    const float r = fmaxf(a2[c][p], 0.0f);
                    sxs[c * 4 + p][tid] = r;
                    lb[p] = fmaf(w[c], r, lb[p]);
                }
            *(float4*)&sl[0][srow][c0] = make_float4(lb[0], lb[1], lb[2], lb[3]);
        }

        // ================= PASS 2: edge head + fused head =================
        {
            float4 f[8];
#pragma unroll
            for (int k = 0; k < 8; k++)
                f[k] = *(const float4*)(fbE + k * HWd + base);

            float acc[8][4];
            lds8(b1eA, w);
#pragma unroll
            for (int c = 0; c < 8; c++)
#pragma unroll
                for (int p = 0; p < 4; p++) acc[c][p] = w[c];
            lds8(w1eT, w);
#pragma unroll
            for (int c = 0; c < 8; c++)
#pragma unroll
                for (int p = 0; p < 4; p++) acc[c][p] = fmaf(w[c], relx[p], acc[c][p]);
            lds8(w1eT + 8, w);
#pragma unroll
            for (int c = 0; c < 8; c++)
#pragma unroll
                for (int p = 0; p < 4; p++) acc[c][p] = fmaf(w[c], rely, acc[c][p]);
#pragma unroll
            for (int k = 0; k < 8; k++) {
                lds8(w1eT + 16 + k * 8, w);
                const float v0 = f[k].x, v1 = f[k].y, v2 = f[k].z, v3 = f[k].w;
#pragma unroll
                for (int c = 0; c < 8; c++) {
                    acc[c][0] = fmaf(w[c], v0, acc[c][0]);
                    acc[c][1] = fmaf(w[c], v1, acc[c][1]);
                    acc[c][2] = fmaf(w[c], v2, acc[c][2]);
                    acc[c][3] = fmaf(w[c], v3, acc[c][3]);
                }
            }
#pragma unroll
            for (int c = 0; c < 8; c++)
#pragma unroll
                for (int p = 0; p < 4; p++) acc[c][p] = fmaxf(acc[c][p], 0.0f);

            float a2[8][4];
            lds8(b2eA, w);
#pragma unroll
            for (int c = 0; c < 8; c++)
#pragma unroll
                for (int p = 0; p < 4; p++) a2[c][p] = w[c];
#pragma unroll
            for (int k = 0; k < 8; k++) {
                lds8(w2eT + k * 8, w);
#pragma unroll
                for (int c = 0; c < 8; c++)
#pragma unroll
                    for (int p = 0; p < 4; p++)
                        a2[c][p] = fmaf(w[c], acc[k][p], a2[c][p]);
            }
            // layer3-e + build fused input xf = relu(a2) + x2b (into acc)
            lds8(w3eA, w);
            float le[4] = {b3e, b3e, b3e, b3e};
#pragma unroll
            for (int c = 0; c < 8; c++)
#pragma unroll
                for (int p = 0; p < 4; p++) {
                    const float r = fmaxf(a2[c][p], 0.0f);
                    le[p] = fmaf(w[c], r, le[p]);
                    acc[c][p] = r + sxs[c * 4 + p][tid];
                }
            *(float4*)&sl[1][srow][c0] = make_float4(le[0], le[1], le[2], le[3]);

            // fused head: 8 -> 8 (relu) -> 1
            float a3[8][4];
            lds8(bf1A, w);
#pragma unroll
            for (int c = 0; c < 8; c++)
#pragma unroll
                for (int p = 0; p < 4; p++) a3[c][p] = w[c];
#pragma unroll
            for (int k = 0; k < 8; k++) {
                lds8(wf1T + k * 8, w);
#pragma unroll
                for (int c = 0; c < 8; c++)
#pragma unroll
                    for (int p = 0; p < 4; p++)
                        a3[c][p] = fmaf(w[c], acc[k][p], a3[c][p]);
            }
            lds8(wf2A, w);
            float lf[4] = {bf2, bf2, bf2, bf2};
#pragma unroll
            for (int c = 0; c < 8; c++)
#pragma unroll
                for (int p = 0; p < 4; p++)
                    lf[p] = fmaf(w[c], fmaxf(a3[c][p], 0.0f), lf[p]);
            *(float4*)&sl[2][srow][c0] = make_float4(lf[0], lf[1], lf[2], lf[3]);
        }
    }
    __syncthreads();

    // ---------------- Phase C: aligned_bilinear x2 + sigmoid ----------------
    const int rows_here = min(OT, OH - i0);
    const int npix      = rows_here * OW;
    const long long ostride = (long long)n_inst * OH * OW;
    float* ob = out + (long long)inst * (OH * OW);

    for (int idx = tid; idx < npix; idx += NT) {
        const int di = idx / OW;
        const int j  = idx - di * OW;
        const int i  = i0 + di;
        const int r  = (i > 0) ? i - 1 : 0;
        const int c  = (j > 0) ? j - 1 : 0;
        const int y0 = r >> 1;
        const int x0 = c >> 1;
        const float fy = (r & 1) ? 0.5f : 0.0f;
        const float fx = (c & 1) ? 0.5f : 0.0f;
        const int y1  = min(y0 + 1, Hh - 1);
        const int x1c = min(x0 + 1, Wd - 1);
        const int s0 = y0 - ybase;
        const int s1 = y1 - ybase;
        const int oidx = i * OW + j;

#pragma unroll
        for (int m = 0; m < 3; m++) {
            const float v00 = sl[m][s0][x0],  v01 = sl[m][s0][x1c];
            const float v10 = sl[m][s1][x0],  v11 = sl[m][s1][x1c];
            const float vt = v00 + fx * (v01 - v00);
            const float vb = v10 + fx * (v11 - v10);
            const float v  = vt + fy * (vb - vt);
            ob[m * ostride + oidx] = __fdividef(1.0f, 1.0f + __expf(-v));
        }
    }
}

extern "C" void kernel_launch(void* const* d_in, const int* in_sizes, int n_in,
                              void* d_out, int out_size)
{
    const float* feats_b = (const float*)d_in[0];
    const float* feats_e = (const float*)d_in[1];
    const float* params  = (const float*)d_in[2];
    const float* locs    = (const float*)d_in[3];
    const float* soi     = (const float*)d_in[4];
    const int*   im      = (const int*)d_in[5];
    const int*   fpn     = (const int*)d_in[6];
    const int*   stridep = (n_in > 7) ? (const int*)d_in[7] : nullptr;

    const int n_inst = in_sizes[5];                 // 128
    dim3 grid((OH + OT - 1) / OT, n_inst);          // 9 x 128
    dmh_kernel<<<grid, NT>>>(feats_b, feats_e, params, locs, soi,
                             im, fpn, stridep, (float*)d_out, n_inst);
}

// round 8
// speedup vs baseline: 1.4652x; 1.4652x over previous
#include <cuda_runtime.h>
#include <cuda_bf16.h>

// DynamicMaskHead fused kernel (R8):
//   R7's k-outer MLP structure (weights transposed to [k][c] -> LDS.128,
//   32-wide FFMA ILP per weight load), but with NO register cap (every capped
//   variant spilled: R2/R3/R7 all pinned at cap with 3+ TB/s local traffic)
//   and `#pragma unroll 1` on the outer group loop to stop ptxas inflating
//   the live range by pipelining across iterations.
//
// Shapes (fixed): feats [2,8,100,152] f32, params [128,419] f32,
//                 out = 3 x [128,1,200,304] f32 concatenated (b,e,f).

#define Hh   100
#define Wd   152
#define HWd  15200
#define OH   200
#define OW   304
#define OT   24      // output rows per block tile (9 tiles)
#define LR   14      // max logits rows per tile (12 + 2 halo)
#define NPAR 419
#define NT   128     // threads per block

// load 8 consecutive floats from 16B-aligned smem as 2x LDS.128
__device__ __forceinline__ void lds8(const float* __restrict__ base, float w[8]) {
    const float4 a = *(const float4*)base;
    const float4 b = *(const float4*)(base + 4);
    w[0] = a.x; w[1] = a.y; w[2] = a.z; w[3] = a.w;
    w[4] = b.x; w[5] = b.y; w[6] = b.z; w[7] = b.w;
}

__global__ void __launch_bounds__(NT)
dmh_kernel(const float* __restrict__ feats_b,
           const float* __restrict__ feats_e,
           const float* __restrict__ params,
           const float* __restrict__ locs,
           const float* __restrict__ soi_arr,
           const int*   __restrict__ im_inds,
           const int*   __restrict__ fpn,
           const int*   __restrict__ stride_ptr,
           float*       __restrict__ out,
           int n_inst)
{
    const int tid  = threadIdx.x;
    const int tile = blockIdx.x;
    const int inst = blockIdx.y;
    const int i0   = tile * OT;

    __shared__ __align__(16) float sp[NPAR];
    __shared__ __align__(16) float sl[3][LR][Wd];
    __shared__ float sxs[32][NT];           // per-thread scratch: x2b[8ch][4pos]
    // transposed weights [k][c] (16B aligned) + aligned bias copies
    __shared__ __align__(16) float w1bT[80], w1eT[80];
    __shared__ __align__(16) float w2bT[64], w2eT[64], wf1T[64];
    __shared__ __align__(16) float w3bA[8], w3eA[8], b1bA[8], b1eA[8];
    __shared__ __align__(16) float b2bA[8], b2eA[8], wf2A[8], bf1A[8];

    const float* prow = params + inst * NPAR;
    for (int t = tid; t < NPAR; t += NT) sp[t] = prow[t];
    __syncthreads();

    // transpose weights to [k][c]; copy misaligned biases into aligned arrays
    if (tid < 80) {                               // 80 threads: w1 (10x8)
        const int k = tid >> 3, c = tid & 7;
        w1bT[tid] = sp[c * 10 + k];
        w1eT[tid] = sp[169 + c * 10 + k];
    }
    if (tid >= 64) {                              // 64 threads: w2/wf (8x8)
        const int t = tid - 64;
        const int k = t >> 3, c = t & 7;
        w2bT[t] = sp[80 + c * 8 + k];
        w2eT[t] = sp[249 + c * 8 + k];
        wf1T[t] = sp[338 + c * 8 + k];
    }
    if (tid < 8) {                                // 8 threads: bias/out-weight
        w3bA[tid] = sp[144 + tid];  w3eA[tid] = sp[313 + tid];
        b1bA[tid] = sp[152 + tid];  b1eA[tid] = sp[321 + tid];
        b2bA[tid] = sp[160 + tid];  b2eA[tid] = sp[329 + tid];
        wf2A[tid] = sp[402 + tid];  bf1A[tid] = sp[410 + tid];
    }

    const int   stride  = stride_ptr ? *stride_ptr : 8;
    const float fstride = (float)stride;
    const float halfs   = (float)(stride >> 1);

    const float ix  = locs[inst * 2 + 0];
    const float iy  = locs[inst * 2 + 1];
    const float inv = 1.0f / soi_arr[fpn[inst]];
    const int   im  = im_inds[inst];

    const int ybase = (i0 > 0) ? ((i0 - 1) >> 1) : 0;
    const int yend  = min(Hh - 1, ((i0 + OT - 2) >> 1) + 1);
    const int nrows = yend - ybase + 1;

    __syncthreads();

    const float b3b = sp[168], b3e = sp[337], bf2 = sp[418];

    const float* fbB = feats_b + (long long)im * 8 * HWd;
    const float* fbE = feats_e + (long long)im * 8 * HWd;

    // ---------------- Phase B: logits strip into smem ----------------
    const int ngroups = nrows * (Wd / 4);      // 38 col-groups per row
#pragma unroll 1
    for (int g = tid; g < ngroups; g += NT) {
        const int srow = g / 38;
        const int c0   = (g - srow * 38) * 4;
        const int y    = ybase + srow;

        const float rely = (iy - ((float)y * fstride + halfs)) * inv;
        float relx[4];
#pragma unroll
        for (int p = 0; p < 4; p++)
            relx[p] = (ix - ((float)(c0 + p) * fstride + halfs)) * inv;

        const int base = y * Wd + c0;
        float w[8];

        // ================= PASS 1: body head =================
        {
            float4 f[8];
#pragma unroll
            for (int k = 0; k < 8; k++)
                f[k] = *(const float4*)(fbB + k * HWd + base);

            // layer1: acc[c][p], k-outer
            float acc[8][4];
            lds8(b1bA, w);
#pragma unroll
            for (int c = 0; c < 8; c++)
#pragma unroll
                for (int p = 0; p < 4; p++) acc[c][p] = w[c];
            lds8(w1bT, w);                          // k=0: relx
#pragma unroll
            for (int c = 0; c < 8; c++)
#pragma unroll
                for (int p = 0; p < 4; p++) acc[c][p] = fmaf(w[c], relx[p], acc[c][p]);
            lds8(w1bT + 8, w);                      // k=1: rely
#pragma unroll
            for (int c = 0; c < 8; c++)
#pragma unroll
                for (int p = 0; p < 4; p++) acc[c][p] = fmaf(w[c], rely, acc[c][p]);
#pragma unroll
            for (int k = 0; k < 8; k++) {
                lds8(w1bT + 16 + k * 8, w);
                const float v0 = f[k].x, v1 = f[k].y, v2 = f[k].z, v3 = f[k].w;
#pragma unroll
                for (int c = 0; c < 8; c++) {
                    acc[c][0] = fmaf(w[c], v0, acc[c][0]);
                    acc[c][1] = fmaf(w[c], v1, acc[c][1]);
                    acc[c][2] = fmaf(w[c], v2, acc[c][2]);
                    acc[c][3] = fmaf(w[c], v3, acc[c][3]);
                }
            }
            // relu in place -> x1
#pragma unroll
            for (int c = 0; c < 8; c++)
#pragma unroll
                for (int p = 0; p < 4; p++) acc[c][p] = fmaxf(acc[c][p], 0.0f);

            // layer2
            float a2[8][4];
            lds8(b2bA, w);
#pragma unroll
            for (int c = 0; c < 8; c++)
#pragma unroll
                for (int p = 0; p < 4; p++) a2[c][p] = w[c];
#pragma unroll
            for (int k = 0; k < 8; k++) {
                lds8(w2bT + k * 8, w);
#pragma unroll
                for (int c = 0; c < 8; c++)
#pragma unroll
                    for (int p = 0; p < 4; p++)
                        a2[c][p] = fmaf(w[c], acc[k][p], a2[c][p]);
            }
            // layer3 + stage x2b
            lds8(w3bA, w);
            float lb[4] = {b3b, b3b, b3b, b3b};
#pragma unroll
            for (int c = 0; c < 8; c++)
#pragma unroll
                for (int p = 0; p < 4; p++) {
                    const float r = fmaxf(a2[c][p], 0.0f);
                    sxs[c * 4 + p][tid] = r;
                    lb[p] = fmaf(w[c], r, lb[p]);
                }
            *(float4*)&sl[0][srow][c0] = make_float4(lb[0], lb[1], lb[2], lb[3]);
        }

        // ================= PASS 2: edge head + fused head =================
        {
            float4 f[8];
#pragma unroll
            for (int k = 0; k < 8; k++)
                f[k] = *(const float4*)(fbE + k * HWd + base);

            float acc[8][4];
            lds8(b1eA, w);
#pragma unroll
            for (int c = 0; c < 8; c++)
#pragma unroll
                for (int p = 0; p < 4; p++) acc[c][p] = w[c];
            lds8(w1eT, w);
#pragma unroll
            for (int c = 0; c < 8; c++)
#pragma unroll
                for (int p = 0; p < 4; p++) acc[c][p] = fmaf(w[c], relx[p], acc[c][p]);
            lds8(w1eT + 8, w);
#pragma unroll
            for (int c = 0; c < 8; c++)
#pragma unroll
                for (int p = 0; p < 4; p++) acc[c][p] = fmaf(w[c], rely, acc[c][p]);
#pragma unroll
            for (int k = 0; k < 8; k++) {
                lds8(w1eT + 16 + k * 8, w);
                const float v0 = f[k].x, v1 = f[k].y, v2 = f[k].z, v3 = f[k].w;
#pragma unroll
                for (int c = 0; c < 8; c++) {
                    acc[c][0] = fmaf(w[c], v0, acc[c][0]);
                    acc[c][1] = fmaf(w[c], v1, acc[c][1]);
                    acc[c][2] = fmaf(w[c], v2, acc[c][2]);
                    acc[c][3] = fmaf(w[c], v3, acc[c][3]);
                }
            }
#pragma unroll
            for (int c = 0; c < 8; c++)
#pragma unroll
                for (int p = 0; p < 4; p++) acc[c][p] = fmaxf(acc[c][p], 0.0f);

            float a2[8][4];
            lds8(b2eA, w);
#pragma unroll
            for (int c = 0; c < 8; c++)
#pragma unroll
                for (int p = 0; p < 4; p++) a2[c][p] = w[c];
#pragma unroll
            for (int k = 0; k < 8; k++) {
                lds8(w2eT + k * 8, w);
#pragma unroll
                for (int c = 0; c < 8; c++)
#pragma unroll
                    for (int p = 0; p < 4; p++)
                        a2[c][p] = fmaf(w[c], acc[k][p], a2[c][p]);
            }
            // layer3-e + build fused input xf = relu(a2) + x2b (into acc)
            lds8(w3eA, w);
            float le[4] = {b3e, b3e, b3e, b3e};
#pragma unroll
            for (int c = 0; c < 8; c++)
#pragma unroll
                for (int p = 0; p < 4; p++) {
                    const float r = fmaxf(a2[c][p], 0.0f);
                    le[p] = fmaf(w[c], r, le[p]);
                    acc[c][p] = r + sxs[c * 4 + p][tid];
                }
            *(float4*)&sl[1][srow][c0] = make_float4(le[0], le[1], le[2], le[3]);

            // fused head: 8 -> 8 (relu) -> 1
            float a3[8][4];
            lds8(bf1A, w);
#pragma unroll
            for (int c = 0; c < 8; c++)
#pragma unroll
                for (int p = 0; p < 4; p++) a3[c][p] = w[c];
#pragma unroll
            for (int k = 0; k < 8; k++) {
                lds8(wf1T + k * 8, w);
#pragma unroll
                for (int c = 0; c < 8; c++)
#pragma unroll
                    for (int p = 0; p < 4; p++)
                        a3[c][p] = fmaf(w[c], acc[k][p], a3[c][p]);
            }
            lds8(wf2A, w);
            float lf[4] = {bf2, bf2, bf2, bf2};
#pragma unroll
            for (int c = 0; c < 8; c++)
#pragma unroll
                for (int p = 0; p < 4; p++)
                    lf[p] = fmaf(w[c], fmaxf(a3[c][p], 0.0f), lf[p]);
            *(float4*)&sl[2][srow][c0] = make_float4(lf[0], lf[1], lf[2], lf[3]);
        }
    }
    __syncthreads();

    // ---------------- Phase C: aligned_bilinear x2 + sigmoid ----------------
    const int rows_here = min(OT, OH - i0);
    const int npix      = rows_here * OW;
    const long long ostride = (long long)n_inst * OH * OW;
    float* ob = out + (long long)inst * (OH * OW);

#pragma unroll 1
    for (int idx = tid; idx < npix; idx += NT) {
        const int di = idx / OW;
        const int j  = idx - di * OW;
        const int i  = i0 + di;
        const int r  = (i > 0) ? i - 1 : 0;
        const int c  = (j > 0) ? j - 1 : 0;
        const int y0 = r >> 1;
        const int x0 = c >> 1;
        const float fy = (r & 1) ? 0.5f : 0.0f;
        const float fx = (c & 1) ? 0.5f : 0.0f;
        const int y1  = min(y0 + 1, Hh - 1);
        const int x1c = min(x0 + 1, Wd - 1);
        const int s0 = y0 - ybase;
        const int s1 = y1 - ybase;
        const int oidx = i * OW + j;

#pragma unroll
        for (int m = 0; m < 3; m++) {
            const float v00 = sl[m][s0][x0],  v01 = sl[m][s0][x1c];
            const float v10 = sl[m][s1][x0],  v11 = sl[m][s1][x1c];
            const float vt = v00 + fx * (v01 - v00);
            const float vb = v10 + fx * (v11 - v10);
            const float v  = vt + fy * (vb - vt);
            ob[m * ostride + oidx] = __fdividef(1.0f, 1.0f + __expf(-v));
        }
    }
}

extern "C" void kernel_launch(void* const* d_in, const int* in_sizes, int n_in,
                              void* d_out, int out_size)
{
    const float* feats_b = (const float*)d_in[0];
    const float* feats_e = (const float*)d_in[1];
    const float* params  = (const float*)d_in[2];
    const float* locs    = (const float*)d_in[3];
    const float* soi     = (const float*)d_in[4];
    const int*   im      = (const int*)d_in[5];
    const int*   fpn     = (const int*)d_in[6];
    const int*   stridep = (n_in > 7) ? (const int*)d_in[7] : nullptr;

    const int n_inst = in_sizes[5];                 // 128
    dim3 grid((OH + OT - 1) / OT, n_inst);          // 9 x 128
    dmh_kernel<<<grid, NT>>>(feats_b, feats_e, params, locs, soi,
                             im, fpn, stridep, (float*)d_out, n_inst);
}